// round 12
// baseline (speedup 1.0000x reference)
#include <cuda_runtime.h>
#include <cuda_fp16.h>
#include <mma.h>
#include <math.h>
#include <stdint.h>

using namespace nvcuda;

// ---------------------------------------------------------------------------
// GAT (3 layers) + mean pool + sigmoid.
// - Layer 1 aggregates RAW x (11-dim) via linearity; logits from x·(W@a).
// - Layer-2 GEMM on wmma; layer-3 GEMM fused into the same kernel.
// - Aggregations: direct-exp softmax, col dedup via lane&7 + shuffle,
//   deferred den reduce, warp-uniform trips. aggr128 adds cross-chunk
//   prefetch of col/as (warp-uniform guard) to raise MLP.
// - CSR count/scatter at 8 edges/thread (batched atomics).
// ---------------------------------------------------------------------------

#define NMAX   50000
#define NPAD   50048
#define EMAX   800000
#define ETOTMX (EMAX + NMAX)
#define HID    128
#define F_IN   11
#define NC     16
#define NG     64
#define SCAN_CHUNK 1024
#define FULLM  0xffffffffu

__device__ __align__(16) __half g_A[NPAD * HID];    // layer-1 output (fp16)
__device__ __align__(16) __half g_G2[NPAD * HID];   // aggr of A (wmma input)
__device__ __align__(16) __half g_h16[NPAD * NC];   // h3 = relu(C)@W3 (fp16)
__device__ __align__(16) __half g_Wh[HID * HID];    // W2 fp16
__device__ __align__(16) __half g_Wh3[HID * NC];    // W3 fp16
__device__ float  g_G1[NMAX * F_IN];                // aggr of x (fp32)
__device__ float  g_as[NMAX];
__device__ float  g_ad[NMAX];
__device__ float  g_ws1[F_IN],  g_wd1[F_IN];
__device__ float  g_ws2[HID],   g_wd2[HID];
__device__ float  g_ws3[HID],   g_wd3[HID];
__device__ float  g_pool[NG * NC];
__device__ float  g_cnt[NG];
__device__ int    g_deg[NMAX];
__device__ int    g_rowptr[NMAX + 1];
__device__ int    g_cursor[NMAX];
__device__ int    g_partial[128];
__device__ int    g_col[ETOTMX];

// --------------------------- setup: zeroing + precompute --------------------
__global__ void setup_kernel(const float* __restrict__ W1,
                             const float* __restrict__ a_s1, const float* __restrict__ a_d1,
                             const float* __restrict__ W2,
                             const float* __restrict__ a_s2, const float* __restrict__ a_d2,
                             const float* __restrict__ W3,
                             const float* __restrict__ a_s3, const float* __restrict__ a_d3,
                             float* __restrict__ ws1, float* __restrict__ wd1,
                             float* __restrict__ ws2, float* __restrict__ wd2,
                             float* __restrict__ ws3, float* __restrict__ wd3,
                             __half* __restrict__ Wh, __half* __restrict__ Wh3,
                             int* __restrict__ deg,
                             float* __restrict__ pool, float* __restrict__ cnt,
                             int n, int nodeBlocks) {
    int b = blockIdx.x, t = threadIdx.x;
    if (b < nodeBlocks) {
        int i = b * 256 + t;
        if (i < n) deg[i] = 0;
        if (i < NG * NC) pool[i] = 0.f;
        if (i < NG) cnt[i] = 0.f;
    } else if (b == nodeBlocks) {
        if (t < HID) {
            float s = 0.f, d = 0.f;
            for (int c = 0; c < HID; c++) {
                float w = __ldg(W2 + t * HID + c);
                s = fmaf(w, __ldg(a_s2 + c), s);
                d = fmaf(w, __ldg(a_d2 + c), d);
            }
            ws2[t] = s; wd2[t] = d;
        } else {
            int k = t - HID;
            float s = 0.f, d = 0.f;
            for (int c = 0; c < NC; c++) {
                float w = __ldg(W3 + k * NC + c);
                s = fmaf(w, __ldg(a_s3 + c), s);
                d = fmaf(w, __ldg(a_d3 + c), d);
            }
            ws3[k] = s; wd3[k] = d;
        }
    } else if (b == nodeBlocks + 1) {
        if (t < F_IN) {
            float s = 0.f, d = 0.f;
            for (int c = 0; c < HID; c++) {
                float w = __ldg(W1 + t * HID + c);
                s = fmaf(w, __ldg(a_s1 + c), s);
                d = fmaf(w, __ldg(a_d1 + c), d);
            }
            ws1[t] = s; wd1[t] = d;
        }
    } else if (b < nodeBlocks + 66) {
        int i = (b - nodeBlocks - 2) * 256 + t;
        if (i < HID * HID) Wh[i] = __float2half_rn(__ldg(W2 + i));
    } else {
        int i = (b - nodeBlocks - 66) * 256 + t;
        if (i < HID * NC) Wh3[i] = __float2half_rn(__ldg(W3 + i));
    }
}

// ----------------- count_deg (8/thread) + layer-1 logits (fused) ------------
__global__ void count_asad_kernel(const int* __restrict__ dst, int E, int Etot,
                                  int* __restrict__ deg,
                                  const float* __restrict__ x,
                                  const float* __restrict__ ws1,
                                  const float* __restrict__ wd1,
                                  float* __restrict__ as_o, float* __restrict__ ad_o,
                                  int n, int edgeBlocks) {
    int b = blockIdx.x, tt = threadIdx.x;
    if (b < edgeBlocks) {
        int t = (b * 256 + tt) * 8;
        int d[8];
#pragma unroll
        for (int j = 0; j < 8; j++) {
            int i = t + j;
            d[j] = (i < Etot) ? (i < E ? __ldg(dst + i) : (i - E)) : -1;
        }
#pragma unroll
        for (int j = 0; j < 8; j++)
            if (d[j] >= 0) atomicAdd(&deg[d[j]], 1);
    } else {
        int i = (b - edgeBlocks) * 256 + tt;
        if (i >= n) return;
        const float* row = x + (size_t)i * F_IN;
        float s = 0.f, d = 0.f;
#pragma unroll
        for (int k = 0; k < F_IN; k++) {
            float v = __ldg(row + k);
            s = fmaf(v, __ldg(ws1 + k), s);
            d = fmaf(v, __ldg(wd1 + k), d);
        }
        as_o[i] = s; ad_o[i] = d;
    }
}

// --------------------------- scan (2 kernels) -------------------------------
__global__ void scan_partial_kernel(const int* __restrict__ deg,
                                    int* __restrict__ partial, int n) {
    __shared__ int ws[8];
    int base = blockIdx.x * SCAN_CHUNK + threadIdx.x * 4;
    int s = 0;
#pragma unroll
    for (int j = 0; j < 4; j++) {
        int i = base + j;
        if (i < n) s += __ldg(deg + i);
    }
#pragma unroll
    for (int o = 16; o > 0; o >>= 1) s += __shfl_xor_sync(FULLM, s, o);
    int lane = threadIdx.x & 31, wid = threadIdx.x >> 5;
    if (lane == 0) ws[wid] = s;
    __syncthreads();
    if (wid == 0 && lane < 8) {
        int v = ws[lane];
#pragma unroll
        for (int o = 4; o > 0; o >>= 1) v += __shfl_xor_sync(0xffu, v, o);
        if (lane == 0) partial[blockIdx.x] = v;
    }
}

__global__ void scan_final_kernel(const int* __restrict__ deg,
                                  const int* __restrict__ partial,
                                  int* __restrict__ rowptr,
                                  int* __restrict__ cursor, int n, int nb) {
    __shared__ int ws[8];
    __shared__ int w2s[2];
    __shared__ int s_off;
    int t = threadIdx.x, lane = t & 31, wid = t >> 5;

    int pv = 0;
    if (t < 64 && t < blockIdx.x && t < nb) pv = __ldg(partial + t);
    if (t < 64) {
#pragma unroll
        for (int o = 16; o > 0; o >>= 1) pv += __shfl_xor_sync(FULLM, pv, o);
        if (lane == 0) w2s[wid] = pv;
    }
    __syncthreads();
    if (t == 0) s_off = w2s[0] + w2s[1];

    int base = blockIdx.x * SCAN_CHUNK + t * 4;
    int v[4];
#pragma unroll
    for (int j = 0; j < 4; j++) {
        int i = base + j;
        v[j] = (i < n) ? __ldg(deg + i) : 0;
    }
    int tot = v[0] + v[1] + v[2] + v[3];
    int x = tot;
#pragma unroll
    for (int o = 1; o < 32; o <<= 1) {
        int u = __shfl_up_sync(FULLM, x, o);
        if (lane >= o) x += u;
    }
    int warp_excl = x - tot;
    if (lane == 31) ws[wid] = x;
    __syncthreads();
    if (wid == 0) {
        int val = (lane < 8) ? ws[lane] : 0;
#pragma unroll
        for (int o = 1; o < 8; o <<= 1) {
            int u = __shfl_up_sync(FULLM, val, o);
            if (lane >= o) val += u;
        }
        if (lane < 8) ws[lane] = val;
    }
    __syncthreads();
    int off = s_off + (wid > 0 ? ws[wid - 1] : 0) + warp_excl;
    int run = off;
#pragma unroll
    for (int j = 0; j < 4; j++) {
        run += v[j];
        int i = base + j;
        if (i < n) { rowptr[i + 1] = run; cursor[i] = run - v[j]; }
    }
    if (blockIdx.x == 0 && t == 0) rowptr[0] = 0;
}

__global__ void scatter_kernel(const int* __restrict__ src, const int* __restrict__ dst,
                               int E, int Etot,
                               int* __restrict__ cursor, int* __restrict__ col) {
    int t = (blockIdx.x * blockDim.x + threadIdx.x) * 8;
    int s[8], d[8];
#pragma unroll
    for (int j = 0; j < 8; j++) {
        int i = t + j;
        bool act = i < Etot;
        s[j] = act ? (i < E ? __ldg(src + i) : (i - E)) : 0;
        d[j] = act ? (i < E ? __ldg(dst + i) : (i - E)) : -1;
    }
    int pos[8];
#pragma unroll
    for (int j = 0; j < 8; j++)
        pos[j] = (d[j] >= 0) ? atomicAdd(&cursor[d[j]], 1) : -1;
#pragma unroll
    for (int j = 0; j < 8; j++)
        if (pos[j] >= 0) col[pos[j]] = s[j];
}

// ------------------ layer-1 aggregation of raw x (11-dim) -------------------
__global__ void aggr11_kernel(const int* __restrict__ rowptr,
                              const int* __restrict__ col,
                              const float* __restrict__ as_v,
                              const float* __restrict__ ad_v,
                              const float* __restrict__ x,
                              float* __restrict__ G, int n) {
    int w = (blockIdx.x * blockDim.x + threadIdx.x) >> 5;
    int lane = threadIdx.x & 31;
    int local = lane & 15;
    int slot = lane & 7;
    int node = w * 2 + (lane >> 4);
    int c = local;
    bool active = node < n;

    float advv = active ? __ldg(ad_v + node) : 0.f;
    int beg = active ? __ldg(rowptr + node) : 0;
    int end = active ? __ldg(rowptr + node + 1) : 0;

    int iters = (end - beg + 7) >> 3;
    int oiters = __shfl_xor_sync(FULLM, iters, 16);
    int maxIters = iters > oiters ? iters : oiters;

    const float NEG_INF = __int_as_float(0xFF800000);
    float denp = 0.0f, acc = 0.0f;

    for (int it = 0; it < maxIters; it++) {
        int idx = beg + it * 8 + slot;
        bool eact = idx < end;
        int sc = __ldg(col + (eact ? idx : 0));
        float e = eact ? (__ldg(as_v + sc) + advv) : NEG_INF;
        e = e > 0.f ? e : 0.2f * e;
        float wgt = __expf(e);
        denp += wgt;

        float xb[8];
#pragma unroll
        for (int j = 0; j < 8; j++) {
            int sj = __shfl_sync(FULLM, sc, j, 16);
            xb[j] = (c < F_IN) ? __ldg(x + (size_t)sj * F_IN + c) : 0.f;
        }
#pragma unroll
        for (int j = 0; j < 8; j++) {
            float wj = __shfl_sync(FULLM, wgt, j, 16);
            acc = fmaf(wj, xb[j], acc);
        }
    }
    denp += __shfl_xor_sync(FULLM, denp, 1, 8);
    denp += __shfl_xor_sync(FULLM, denp, 2, 8);
    denp += __shfl_xor_sync(FULLM, denp, 4, 8);
    if (active && c < F_IN) G[(size_t)node * F_IN + c] = acc / denp;
}

// --------------- layer-1 GEMM: A = relu(G1@W1+b1), epi: as2/ad2 -------------
__global__ void gemmK11_kernel(const float* __restrict__ in,
                               const float* __restrict__ W,
                               const float* __restrict__ bias,
                               const float* __restrict__ ws2,
                               const float* __restrict__ wd2,
                               __half* __restrict__ A,
                               float* __restrict__ as_o,
                               float* __restrict__ ad_o, int n) {
    int w    = (blockIdx.x * blockDim.x + threadIdx.x) >> 5;
    int lane = threadIdx.x & 31;
    int node0 = w * 8;
    if (node0 >= n) return;

    int nid[8];
#pragma unroll
    for (int i = 0; i < 8; i++) {
        int nn = node0 + i;
        nid[i] = nn < n ? nn : (n - 1);
    }

    float4 bv = *(const float4*)(bias + lane * 4);
    float4 acc[8];
#pragma unroll
    for (int i = 0; i < 8; i++) acc[i] = bv;

#pragma unroll
    for (int k = 0; k < F_IN; k++) {
        float4 wv = *(const float4*)(W + k * HID + lane * 4);
#pragma unroll
        for (int i = 0; i < 8; i++) {
            float a = __ldg(in + (size_t)nid[i] * F_IN + k);
            acc[i].x = fmaf(a, wv.x, acc[i].x);
            acc[i].y = fmaf(a, wv.y, acc[i].y);
            acc[i].z = fmaf(a, wv.z, acc[i].z);
            acc[i].w = fmaf(a, wv.w, acc[i].w);
        }
    }

    float4 sv = *(const float4*)(ws2 + lane * 4);
    float4 dv = *(const float4*)(wd2 + lane * 4);

#pragma unroll
    for (int i = 0; i < 8; i++) {
        float ox = fmaxf(acc[i].x, 0.f);
        float oy = fmaxf(acc[i].y, 0.f);
        float oz = fmaxf(acc[i].z, 0.f);
        float ow = fmaxf(acc[i].w, 0.f);
        __half2 p0 = __floats2half2_rn(ox, oy);
        __half2 p1 = __floats2half2_rn(oz, ow);
        uint2 packed = make_uint2(*(unsigned*)&p0, *(unsigned*)&p1);
        *(uint2*)(A + (size_t)nid[i] * HID + lane * 4) = packed;

        float ps = ox * sv.x + oy * sv.y + oz * sv.z + ow * sv.w;
        float pd = ox * dv.x + oy * dv.y + oz * dv.z + ow * dv.w;
#pragma unroll
        for (int o = 16; o > 0; o >>= 1) {
            ps += __shfl_xor_sync(FULLM, ps, o);
            pd += __shfl_xor_sync(FULLM, pd, o);
        }
        if (lane == 0) { as_o[nid[i]] = ps; ad_o[nid[i]] = pd; }
    }
}

// ------------------ raw softmax aggregation, C=128 (fp16) -------------------
// warp per node; direct-exp; col dedup; CROSS-CHUNK prefetch of col/as
// (guard i+8<end is warp-uniform -> full shuffle participation).
__global__ void aggr128_raw_kernel(const int* __restrict__ rowptr,
                                   const int* __restrict__ col,
                                   const float* __restrict__ as_v,
                                   const float* __restrict__ ad_v,
                                   const __half* __restrict__ h,
                                   __half* __restrict__ out, int n) {
    int node = (blockIdx.x * blockDim.x + threadIdx.x) >> 5;
    if (node >= n) return;
    int lane = threadIdx.x & 31;
    int slot = lane & 7;

    float advv = __ldg(ad_v + node);
    int beg = __ldg(rowptr + node);
    int end = __ldg(rowptr + node + 1);

    const float NEG_INF = __int_as_float(0xFF800000);
    float denp = 0.0f;
    float4 acc = make_float4(0.f, 0.f, 0.f, 0.f);

    // prologue: first chunk's col/as
    int idx0 = beg + slot;
    bool ea0 = idx0 < end;
    int   sc = __ldg(col + (ea0 ? idx0 : beg));
    float e  = ea0 ? (__ldg(as_v + sc) + advv) : NEG_INF;
    e = e > 0.f ? e : 0.2f * e;

    for (int i = beg; i < end; i += 8) {
        float wgt = __expf(e);
        denp += wgt;

        // prefetch next chunk (warp-uniform guard)
        int sc2 = sc; float e2 = NEG_INF;
        if (i + 8 < end) {
            int idx2 = i + 8 + slot;
            bool ea2 = idx2 < end;
            sc2 = __ldg(col + (ea2 ? idx2 : beg));
            e2  = ea2 ? (__ldg(as_v + sc2) + advv) : NEG_INF;
            e2 = e2 > 0.f ? e2 : 0.2f * e2;
        }

        uint2 hb[8];
#pragma unroll
        for (int j = 0; j < 8; j++) {
            int sj = __shfl_sync(FULLM, sc, j);
            hb[j] = *(const uint2*)(h + (size_t)sj * HID + lane * 4);
        }
#pragma unroll
        for (int j = 0; j < 8; j++) {
            float wj = __shfl_sync(FULLM, wgt, j);
            __half2 h0 = *(__half2*)&hb[j].x;
            __half2 h1 = *(__half2*)&hb[j].y;
            float2 f0 = __half22float2(h0);
            float2 f1 = __half22float2(h1);
            acc.x = fmaf(wj, f0.x, acc.x);
            acc.y = fmaf(wj, f0.y, acc.y);
            acc.z = fmaf(wj, f1.x, acc.z);
            acc.w = fmaf(wj, f1.y, acc.w);
        }
        sc = sc2; e = e2;
    }

    denp += __shfl_xor_sync(FULLM, denp, 1, 8);
    denp += __shfl_xor_sync(FULLM, denp, 2, 8);
    denp += __shfl_xor_sync(FULLM, denp, 4, 8);

    float inv = 1.0f / denp;
    __half2 p0 = __floats2half2_rn(acc.x * inv, acc.y * inv);
    __half2 p1 = __floats2half2_rn(acc.z * inv, acc.w * inv);
    uint2 packed = make_uint2(*(unsigned*)&p0, *(unsigned*)&p1);
    *(uint2*)(out + (size_t)node * HID + lane * 4) = packed;
}

// ---- layer-2 wmma GEMM + fused layer-3 GEMM --------------------------------
__global__ __launch_bounds__(128) void wmma_fused_kernel(
        const __half* __restrict__ A,
        const __half* __restrict__ Wh,
        const __half* __restrict__ Wh3,
        const float* __restrict__ bias,
        const float* __restrict__ ws3,
        const float* __restrict__ wd3,
        __half* __restrict__ h16,
        float* __restrict__ as_o,
        float* __restrict__ ad_o, int nPad, int n) {
    __shared__ float  s_c[64 * HID];
    __shared__ __half s_ch[64 * HID];
    int warp = threadIdx.x >> 5;
    int lane = threadIdx.x & 31;
    int row0 = blockIdx.x * 64 + warp * 16;
    if (row0 >= nPad) return;

    wmma::fragment<wmma::accumulator, 16, 16, 16, float> acc[8];
#pragma unroll
    for (int i = 0; i < 8; i++) wmma::fill_fragment(acc[i], 0.f);

#pragma unroll
    for (int k = 0; k < 8; k++) {
        wmma::fragment<wmma::matrix_a, 16, 16, 16, __half, wmma::row_major> a;
        wmma::load_matrix_sync(a, A + (size_t)row0 * HID + k * 16, HID);
#pragma unroll
        for (int nt = 0; nt < 8; nt++) {
            wmma::fragment<wmma::matrix_b, 16, 16, 16, __half, wmma::row_major> b;
            wmma::load_matrix_sync(b, Wh + k * 16 * HID + nt * 16, HID);
            wmma::mma_sync(acc[nt], a, b, acc[nt]);
        }
    }
    float*  my  = s_c  + warp * 16 * HID;
    __half* myh = s_ch + warp * 16 * HID;
#pragma unroll
    for (int nt = 0; nt < 8; nt++)
        wmma::store_matrix_sync(my + nt * 16, acc[nt], HID, wmma::mem_row_major);
    __syncwarp();

    float4 bv = *(const float4*)(bias + lane * 4);
    float4 sv = *(const float4*)(ws3 + lane * 4);
    float4 dv = *(const float4*)(wd3 + lane * 4);
#pragma unroll
    for (int r = 0; r < 16; r++) {
        int row = row0 + r;
        float4 v = *(const float4*)(my + r * HID + lane * 4);
        float ox = fmaxf(v.x + bv.x, 0.f);
        float oy = fmaxf(v.y + bv.y, 0.f);
        float oz = fmaxf(v.z + bv.z, 0.f);
        float ow = fmaxf(v.w + bv.w, 0.f);
        __half2 p0 = __floats2half2_rn(ox, oy);
        __half2 p1 = __floats2half2_rn(oz, ow);
        uint2 packed = make_uint2(*(unsigned*)&p0, *(unsigned*)&p1);
        *(uint2*)(myh + r * HID + lane * 4) = packed;
        if (row < n) {
            float ps = ox * sv.x + oy * sv.y + oz * sv.z + ow * sv.w;
            float pd = ox * dv.x + oy * dv.y + oz * dv.z + ow * dv.w;
#pragma unroll
            for (int o = 16; o > 0; o >>= 1) {
                ps += __shfl_xor_sync(FULLM, ps, o);
                pd += __shfl_xor_sync(FULLM, pd, o);
            }
            if (lane == 0) { as_o[row] = ps; ad_o[row] = pd; }
        }
    }
    __syncwarp();

    wmma::fragment<wmma::accumulator, 16, 16, 16, float> acc3;
    wmma::fill_fragment(acc3, 0.f);
#pragma unroll
    for (int k = 0; k < 8; k++) {
        wmma::fragment<wmma::matrix_a, 16, 16, 16, __half, wmma::row_major> a;
        wmma::load_matrix_sync(a, myh + k * 16, HID);
        wmma::fragment<wmma::matrix_b, 16, 16, 16, __half, wmma::row_major> b;
        wmma::load_matrix_sync(b, Wh3 + k * 16 * NC, NC);
        wmma::mma_sync(acc3, a, b, acc3);
    }
    wmma::store_matrix_sync(my, acc3, NC, wmma::mem_row_major);
    __syncwarp();
#pragma unroll
    for (int q = 0; q < 8; q++) {
        int idx = q * 32 + lane;
        h16[(size_t)row0 * NC + idx] = __float2half_rn(my[idx]);
    }
}

// ------------- fused aggregation C=16 + pooling (layer 3) -------------------
__global__ void fused_aggr16_pool_kernel(const int* __restrict__ rowptr,
                                         const int* __restrict__ col,
                                         const float* __restrict__ as_v,
                                         const float* __restrict__ ad_v,
                                         const __half* __restrict__ h,
                                         const float* __restrict__ bias,
                                         const int* __restrict__ batch,
                                         float* __restrict__ pool,
                                         float* __restrict__ cnt, int n) {
    int w = (blockIdx.x * blockDim.x + threadIdx.x) >> 5;
    int lane = threadIdx.x & 31;
    int local = lane & 15;
    int slot = lane & 7;
    int node = w * 2 + (lane >> 4);
    int c = local;
    bool active = node < n;

    float advv = active ? __ldg(ad_v + node) : 0.f;
    int beg = active ? __ldg(rowptr + node) : 0;
    int end = active ? __ldg(rowptr + node + 1) : 0;

    int iters = (end - beg + 7) >> 3;
    int oiters = __shfl_xor_sync(FULLM, iters, 16);
    int maxIters = iters > oiters ? iters : oiters;

    const float NEG_INF = __int_as_float(0xFF800000);
    float denp = 0.0f, acc = 0.0f;

    for (int it = 0; it < maxIters; it++) {
        int idx = beg + it * 8 + slot;
        bool eact = idx < end;
        int sc = __ldg(col + (eact ? idx : 0));
        float e = eact ? (__ldg(as_v + sc) + advv) : NEG_INF;
        e = e > 0.f ? e : 0.2f * e;
        float wgt = __expf(e);
        denp += wgt;

        float hb[8];
#pragma unroll
        for (int j = 0; j < 8; j++) {
            int sj = __shfl_sync(FULLM, sc, j, 16);
            hb[j] = __half2float(__ldg(h + (size_t)sj * NC + c));
        }
#pragma unroll
        for (int j = 0; j < 8; j++) {
            float wj = __shfl_sync(FULLM, wgt, j, 16);
            acc = fmaf(wj, hb[j], acc);
        }
    }

    denp += __shfl_xor_sync(FULLM, denp, 1, 8);
    denp += __shfl_xor_sync(FULLM, denp, 2, 8);
    denp += __shfl_xor_sync(FULLM, denp, 4, 8);

    if (active) {
        float val = fmaxf(acc / denp + __ldg(bias + c), 0.f);
        int g = __ldg(batch + node);
        atomicAdd(&pool[g * NC + c], val);
        if (c == 0) atomicAdd(&cnt[g], 1.0f);
    }
}

__global__ void finalize_kernel(const float* __restrict__ pool,
                                const float* __restrict__ cnt,
                                float* __restrict__ outp) {
    int t = blockIdx.x * blockDim.x + threadIdx.x;
    if (t >= NG * NC) return;
    int g = t >> 4;
    float v = pool[t] / fmaxf(cnt[g], 1.0f);
    outp[t] = 1.0f / (1.0f + expf(-v));
}

// ---------------------------------------------------------------------------

extern "C" void kernel_launch(void* const* d_in, const int* in_sizes, int n_in,
                              void* d_out, int out_size) {
    const float* x     = (const float*)d_in[0];
    const int*   ei    = (const int*)  d_in[1];
    const int*   batch = (const int*)  d_in[3];
    const float* W1  = (const float*)d_in[4];
    const float* as1 = (const float*)d_in[5];
    const float* ad1 = (const float*)d_in[6];
    const float* b1  = (const float*)d_in[7];
    const float* W2  = (const float*)d_in[8];
    const float* as2 = (const float*)d_in[9];
    const float* ad2 = (const float*)d_in[10];
    const float* b2  = (const float*)d_in[11];
    const float* W3  = (const float*)d_in[12];
    const float* as3 = (const float*)d_in[13];
    const float* ad3 = (const float*)d_in[14];
    const float* b3  = (const float*)d_in[15];
    float* out = (float*)d_out;

    int n    = in_sizes[0] / F_IN;
    int E    = in_sizes[1] / 2;
    int Etot = E + n;
    const int* src = ei;
    const int* dst = ei + E;

    float *pas, *pad, *ppool, *pcnt, *pG1;
    float *pws1, *pwd1, *pws2, *pwd2, *pws3, *pwd3;
    __half *pA, *pG2, *ph16, *pWh, *pWh3;
    int *pdeg, *prow, *pcur, *pcol, *ppart;
    cudaGetSymbolAddress((void**)&pA,    g_A);
    cudaGetSymbolAddress((void**)&pG2,   g_G2);
    cudaGetSymbolAddress((void**)&ph16,  g_h16);
    cudaGetSymbolAddress((void**)&pWh,   g_Wh);
    cudaGetSymbolAddress((void**)&pWh3,  g_Wh3);
    cudaGetSymbolAddress((void**)&pG1,   g_G1);
    cudaGetSymbolAddress((void**)&pas,   g_as);
    cudaGetSymbolAddress((void**)&pad,   g_ad);
    cudaGetSymbolAddress((void**)&pws1,  g_ws1);
    cudaGetSymbolAddress((void**)&pwd1,  g_wd1);
    cudaGetSymbolAddress((void**)&pws2,  g_ws2);
    cudaGetSymbolAddress((void**)&pwd2,  g_wd2);
    cudaGetSymbolAddress((void**)&pws3,  g_ws3);
    cudaGetSymbolAddress((void**)&pwd3,  g_wd3);
    cudaGetSymbolAddress((void**)&ppool, g_pool);
    cudaGetSymbolAddress((void**)&pcnt,  g_cnt);
    cudaGetSymbolAddress((void**)&pdeg,  g_deg);
    cudaGetSymbolAddress((void**)&prow,  g_rowptr);
    cudaGetSymbolAddress((void**)&pcur,  g_cursor);
    cudaGetSymbolAddress((void**)&pcol,  g_col);
    cudaGetSymbolAddress((void**)&ppart, g_partial);

    const int TB = 256;
    int nPad     = (n + 127) & ~127;
    int nb       = (n + SCAN_CHUNK - 1) / SCAN_CHUNK;
    int gN       = (n + TB - 1) / TB;
    int gEdge8   = (Etot + TB * 8 - 1) / (TB * 8);
    int warps128 = (n + 7) / 8;
    int gGemmK11 = (warps128 * 32 + TB - 1) / TB;
    int gWmma    = nPad / 64;
    int gNodeWarp= (n * 32 + TB - 1) / TB;
    int gHalfWarp= (((n + 1) / 2) * 32 + TB - 1) / TB;
    int gPool    = (NG * NC + TB - 1) / TB;

    setup_kernel<<<gN + 74, TB>>>(W1, as1, ad1, W2, as2, ad2, W3, as3, ad3,
                                  pws1, pwd1, pws2, pwd2, pws3, pwd3,
                                  pWh, pWh3, pdeg, ppool, pcnt, n, gN);
    count_asad_kernel<<<gEdge8 + gN, TB>>>(dst, E, Etot, pdeg, x, pws1, pwd1,
                                           pas, pad, n, gEdge8);
    scan_partial_kernel<<<nb, 256>>>(pdeg, ppart, n);
    scan_final_kernel<<<nb, 256>>>(pdeg, ppart, prow, pcur, n, nb);
    scatter_kernel<<<gEdge8, TB>>>(src, dst, E, Etot, pcur, pcol);

    aggr11_kernel<<<gHalfWarp, TB>>>(prow, pcol, pas, pad, x, pG1, n);
    gemmK11_kernel<<<gGemmK11, TB>>>(pG1, W1, b1, pws2, pwd2, pA, pas, pad, n);

    aggr128_raw_kernel<<<gNodeWarp, TB>>>(prow, pcol, pas, pad, pA, pG2, n);
    wmma_fused_kernel<<<gWmma, 128>>>(pG2, pWh, pWh3, b2, pws3, pwd3,
                                      ph16, pas, pad, nPad, n);

    fused_aggr16_pool_kernel<<<gHalfWarp, TB>>>(prow, pcol, pas, pad, ph16, b3,
                                                batch, ppool, pcnt, n);
    finalize_kernel<<<gPool, TB>>>(ppool, pcnt, out);
}

// round 13
// speedup vs baseline: 1.0050x; 1.0050x over previous
#include <cuda_runtime.h>
#include <cuda_fp16.h>
#include <mma.h>
#include <math.h>
#include <stdint.h>

using namespace nvcuda;

// ---------------------------------------------------------------------------
// GAT (3 layers) + mean pool + sigmoid.
// - Layer 1 aggregates RAW x (11-dim) via linearity; logits from x·(W@a).
// - Layer-2 GEMM on wmma; layer-3 GEMM fused into the same kernel.
// - aggr128: 2-edges-per-step uint4 gather (16 lanes cover a 256B row; low
//   half = even edges, high half = odd edges; combine via shfl_xor 16).
//   Halves LDG + shuffle count vs the per-edge uint2 scheme.
// - direct-exp softmax, warp-uniform trips in half-warp kernels.
// ---------------------------------------------------------------------------

#define NMAX   50000
#define NPAD   50048
#define EMAX   800000
#define ETOTMX (EMAX + NMAX)
#define HID    128
#define F_IN   11
#define NC     16
#define NG     64
#define SCAN_CHUNK 1024
#define FULLM  0xffffffffu

__device__ __align__(16) __half g_A[NPAD * HID];    // layer-1 output (fp16)
__device__ __align__(16) __half g_G2[NPAD * HID];   // aggr of A (wmma input)
__device__ __align__(16) __half g_h16[NPAD * NC];   // h3 = relu(C)@W3 (fp16)
__device__ __align__(16) __half g_Wh[HID * HID];    // W2 fp16
__device__ __align__(16) __half g_Wh3[HID * NC];    // W3 fp16
__device__ float  g_G1[NMAX * F_IN];                // aggr of x (fp32)
__device__ float  g_as[NMAX];
__device__ float  g_ad[NMAX];
__device__ float  g_ws1[F_IN],  g_wd1[F_IN];
__device__ float  g_ws2[HID],   g_wd2[HID];
__device__ float  g_ws3[HID],   g_wd3[HID];
__device__ float  g_pool[NG * NC];
__device__ float  g_cnt[NG];
__device__ int    g_deg[NMAX];
__device__ int    g_rowptr[NMAX + 1];
__device__ int    g_cursor[NMAX];
__device__ int    g_partial[128];
__device__ int    g_col[ETOTMX];

// --------------------------- setup: zeroing + precompute --------------------
__global__ void setup_kernel(const float* __restrict__ W1,
                             const float* __restrict__ a_s1, const float* __restrict__ a_d1,
                             const float* __restrict__ W2,
                             const float* __restrict__ a_s2, const float* __restrict__ a_d2,
                             const float* __restrict__ W3,
                             const float* __restrict__ a_s3, const float* __restrict__ a_d3,
                             float* __restrict__ ws1, float* __restrict__ wd1,
                             float* __restrict__ ws2, float* __restrict__ wd2,
                             float* __restrict__ ws3, float* __restrict__ wd3,
                             __half* __restrict__ Wh, __half* __restrict__ Wh3,
                             int* __restrict__ deg,
                             float* __restrict__ pool, float* __restrict__ cnt,
                             int n, int nodeBlocks) {
    int b = blockIdx.x, t = threadIdx.x;
    if (b < nodeBlocks) {
        int i = b * 256 + t;
        if (i < n) deg[i] = 0;
        if (i < NG * NC) pool[i] = 0.f;
        if (i < NG) cnt[i] = 0.f;
    } else if (b == nodeBlocks) {
        if (t < HID) {
            float s = 0.f, d = 0.f;
            for (int c = 0; c < HID; c++) {
                float w = __ldg(W2 + t * HID + c);
                s = fmaf(w, __ldg(a_s2 + c), s);
                d = fmaf(w, __ldg(a_d2 + c), d);
            }
            ws2[t] = s; wd2[t] = d;
        } else {
            int k = t - HID;
            float s = 0.f, d = 0.f;
            for (int c = 0; c < NC; c++) {
                float w = __ldg(W3 + k * NC + c);
                s = fmaf(w, __ldg(a_s3 + c), s);
                d = fmaf(w, __ldg(a_d3 + c), d);
            }
            ws3[k] = s; wd3[k] = d;
        }
    } else if (b == nodeBlocks + 1) {
        if (t < F_IN) {
            float s = 0.f, d = 0.f;
            for (int c = 0; c < HID; c++) {
                float w = __ldg(W1 + t * HID + c);
                s = fmaf(w, __ldg(a_s1 + c), s);
                d = fmaf(w, __ldg(a_d1 + c), d);
            }
            ws1[t] = s; wd1[t] = d;
        }
    } else if (b < nodeBlocks + 66) {
        int i = (b - nodeBlocks - 2) * 256 + t;
        if (i < HID * HID) Wh[i] = __float2half_rn(__ldg(W2 + i));
    } else {
        int i = (b - nodeBlocks - 66) * 256 + t;
        if (i < HID * NC) Wh3[i] = __float2half_rn(__ldg(W3 + i));
    }
}

// ----------------- count_deg + layer-1 logits (fused) -----------------------
__global__ void count_asad_kernel(const int* __restrict__ dst, int E, int Etot,
                                  int* __restrict__ deg,
                                  const float* __restrict__ x,
                                  const float* __restrict__ ws1,
                                  const float* __restrict__ wd1,
                                  float* __restrict__ as_o, float* __restrict__ ad_o,
                                  int n, int edgeBlocks) {
    int b = blockIdx.x, tt = threadIdx.x;
    if (b < edgeBlocks) {
        int t = (b * 256 + tt) * 8;
        int d[8];
#pragma unroll
        for (int j = 0; j < 8; j++) {
            int i = t + j;
            d[j] = (i < Etot) ? (i < E ? __ldg(dst + i) : (i - E)) : -1;
        }
#pragma unroll
        for (int j = 0; j < 8; j++)
            if (d[j] >= 0) atomicAdd(&deg[d[j]], 1);
    } else {
        int i = (b - edgeBlocks) * 256 + tt;
        if (i >= n) return;
        const float* row = x + (size_t)i * F_IN;
        float s = 0.f, d = 0.f;
#pragma unroll
        for (int k = 0; k < F_IN; k++) {
            float v = __ldg(row + k);
            s = fmaf(v, __ldg(ws1 + k), s);
            d = fmaf(v, __ldg(wd1 + k), d);
        }
        as_o[i] = s; ad_o[i] = d;
    }
}

// --------------------------- scan (2 kernels) -------------------------------
__global__ void scan_partial_kernel(const int* __restrict__ deg,
                                    int* __restrict__ partial, int n) {
    __shared__ int ws[8];
    int base = blockIdx.x * SCAN_CHUNK + threadIdx.x * 4;
    int s = 0;
#pragma unroll
    for (int j = 0; j < 4; j++) {
        int i = base + j;
        if (i < n) s += __ldg(deg + i);
    }
#pragma unroll
    for (int o = 16; o > 0; o >>= 1) s += __shfl_xor_sync(FULLM, s, o);
    int lane = threadIdx.x & 31, wid = threadIdx.x >> 5;
    if (lane == 0) ws[wid] = s;
    __syncthreads();
    if (wid == 0 && lane < 8) {
        int v = ws[lane];
#pragma unroll
        for (int o = 4; o > 0; o >>= 1) v += __shfl_xor_sync(0xffu, v, o);
        if (lane == 0) partial[blockIdx.x] = v;
    }
}

__global__ void scan_final_kernel(const int* __restrict__ deg,
                                  const int* __restrict__ partial,
                                  int* __restrict__ rowptr,
                                  int* __restrict__ cursor, int n, int nb) {
    __shared__ int ws[8];
    __shared__ int w2s[2];
    __shared__ int s_off;
    int t = threadIdx.x, lane = t & 31, wid = t >> 5;

    int pv = 0;
    if (t < 64 && t < blockIdx.x && t < nb) pv = __ldg(partial + t);
    if (t < 64) {
#pragma unroll
        for (int o = 16; o > 0; o >>= 1) pv += __shfl_xor_sync(FULLM, pv, o);
        if (lane == 0) w2s[wid] = pv;
    }
    __syncthreads();
    if (t == 0) s_off = w2s[0] + w2s[1];

    int base = blockIdx.x * SCAN_CHUNK + t * 4;
    int v[4];
#pragma unroll
    for (int j = 0; j < 4; j++) {
        int i = base + j;
        v[j] = (i < n) ? __ldg(deg + i) : 0;
    }
    int tot = v[0] + v[1] + v[2] + v[3];
    int x = tot;
#pragma unroll
    for (int o = 1; o < 32; o <<= 1) {
        int u = __shfl_up_sync(FULLM, x, o);
        if (lane >= o) x += u;
    }
    int warp_excl = x - tot;
    if (lane == 31) ws[wid] = x;
    __syncthreads();
    if (wid == 0) {
        int val = (lane < 8) ? ws[lane] : 0;
#pragma unroll
        for (int o = 1; o < 8; o <<= 1) {
            int u = __shfl_up_sync(FULLM, val, o);
            if (lane >= o) val += u;
        }
        if (lane < 8) ws[lane] = val;
    }
    __syncthreads();
    int off = s_off + (wid > 0 ? ws[wid - 1] : 0) + warp_excl;
    int run = off;
#pragma unroll
    for (int j = 0; j < 4; j++) {
        run += v[j];
        int i = base + j;
        if (i < n) { rowptr[i + 1] = run; cursor[i] = run - v[j]; }
    }
    if (blockIdx.x == 0 && t == 0) rowptr[0] = 0;
}

__global__ void scatter_kernel(const int* __restrict__ src, const int* __restrict__ dst,
                               int E, int Etot,
                               int* __restrict__ cursor, int* __restrict__ col) {
    int t = (blockIdx.x * blockDim.x + threadIdx.x) * 8;
    int s[8], d[8];
#pragma unroll
    for (int j = 0; j < 8; j++) {
        int i = t + j;
        bool act = i < Etot;
        s[j] = act ? (i < E ? __ldg(src + i) : (i - E)) : 0;
        d[j] = act ? (i < E ? __ldg(dst + i) : (i - E)) : -1;
    }
    int pos[8];
#pragma unroll
    for (int j = 0; j < 8; j++)
        pos[j] = (d[j] >= 0) ? atomicAdd(&cursor[d[j]], 1) : -1;
#pragma unroll
    for (int j = 0; j < 8; j++)
        if (pos[j] >= 0) col[pos[j]] = s[j];
}

// ------------------ layer-1 aggregation of raw x (11-dim) -------------------
__global__ void aggr11_kernel(const int* __restrict__ rowptr,
                              const int* __restrict__ col,
                              const float* __restrict__ as_v,
                              const float* __restrict__ ad_v,
                              const float* __restrict__ x,
                              float* __restrict__ G, int n) {
    int w = (blockIdx.x * blockDim.x + threadIdx.x) >> 5;
    int lane = threadIdx.x & 31;
    int local = lane & 15;
    int slot = lane & 7;
    int node = w * 2 + (lane >> 4);
    int c = local;
    bool active = node < n;

    float advv = active ? __ldg(ad_v + node) : 0.f;
    int beg = active ? __ldg(rowptr + node) : 0;
    int end = active ? __ldg(rowptr + node + 1) : 0;

    int iters = (end - beg + 7) >> 3;
    int oiters = __shfl_xor_sync(FULLM, iters, 16);
    int maxIters = iters > oiters ? iters : oiters;

    const float NEG_INF = __int_as_float(0xFF800000);
    float denp = 0.0f, acc = 0.0f;

    for (int it = 0; it < maxIters; it++) {
        int idx = beg + it * 8 + slot;
        bool eact = idx < end;
        int sc = __ldg(col + (eact ? idx : 0));
        float e = eact ? (__ldg(as_v + sc) + advv) : NEG_INF;
        e = e > 0.f ? e : 0.2f * e;
        float wgt = __expf(e);
        denp += wgt;

        float xb[8];
#pragma unroll
        for (int j = 0; j < 8; j++) {
            int sj = __shfl_sync(FULLM, sc, j, 16);
            xb[j] = (c < F_IN) ? __ldg(x + (size_t)sj * F_IN + c) : 0.f;
        }
#pragma unroll
        for (int j = 0; j < 8; j++) {
            float wj = __shfl_sync(FULLM, wgt, j, 16);
            acc = fmaf(wj, xb[j], acc);
        }
    }
    denp += __shfl_xor_sync(FULLM, denp, 1, 8);
    denp += __shfl_xor_sync(FULLM, denp, 2, 8);
    denp += __shfl_xor_sync(FULLM, denp, 4, 8);
    if (active && c < F_IN) G[(size_t)node * F_IN + c] = acc / denp;
}

// --------------- layer-1 GEMM: A = relu(G1@W1+b1), epi: as2/ad2 -------------
__global__ void gemmK11_kernel(const float* __restrict__ in,
                               const float* __restrict__ W,
                               const float* __restrict__ bias,
                               const float* __restrict__ ws2,
                               const float* __restrict__ wd2,
                               __half* __restrict__ A,
                               float* __restrict__ as_o,
                               float* __restrict__ ad_o, int n) {
    int w    = (blockIdx.x * blockDim.x + threadIdx.x) >> 5;
    int lane = threadIdx.x & 31;
    int node0 = w * 8;
    if (node0 >= n) return;

    int nid[8];
#pragma unroll
    for (int i = 0; i < 8; i++) {
        int nn = node0 + i;
        nid[i] = nn < n ? nn : (n - 1);
    }

    float4 bv = *(const float4*)(bias + lane * 4);
    float4 acc[8];
#pragma unroll
    for (int i = 0; i < 8; i++) acc[i] = bv;

#pragma unroll
    for (int k = 0; k < F_IN; k++) {
        float4 wv = *(const float4*)(W + k * HID + lane * 4);
#pragma unroll
        for (int i = 0; i < 8; i++) {
            float a = __ldg(in + (size_t)nid[i] * F_IN + k);
            acc[i].x = fmaf(a, wv.x, acc[i].x);
            acc[i].y = fmaf(a, wv.y, acc[i].y);
            acc[i].z = fmaf(a, wv.z, acc[i].z);
            acc[i].w = fmaf(a, wv.w, acc[i].w);
        }
    }

    float4 sv = *(const float4*)(ws2 + lane * 4);
    float4 dv = *(const float4*)(wd2 + lane * 4);

#pragma unroll
    for (int i = 0; i < 8; i++) {
        float ox = fmaxf(acc[i].x, 0.f);
        float oy = fmaxf(acc[i].y, 0.f);
        float oz = fmaxf(acc[i].z, 0.f);
        float ow = fmaxf(acc[i].w, 0.f);
        __half2 p0 = __floats2half2_rn(ox, oy);
        __half2 p1 = __floats2half2_rn(oz, ow);
        uint2 packed = make_uint2(*(unsigned*)&p0, *(unsigned*)&p1);
        *(uint2*)(A + (size_t)nid[i] * HID + lane * 4) = packed;

        float ps = ox * sv.x + oy * sv.y + oz * sv.z + ow * sv.w;
        float pd = ox * dv.x + oy * dv.y + oz * dv.z + ow * dv.w;
#pragma unroll
        for (int o = 16; o > 0; o >>= 1) {
            ps += __shfl_xor_sync(FULLM, ps, o);
            pd += __shfl_xor_sync(FULLM, pd, o);
        }
        if (lane == 0) { as_o[nid[i]] = ps; ad_o[nid[i]] = pd; }
    }
}

// ------------------ raw softmax aggregation, C=128 (fp16) -------------------
// warp per node; lane owns 8 cols (uint4). Low half-warp gathers even edges,
// high half odd edges; halves combined via shfl_xor(16) at the end.
__global__ void aggr128_raw_kernel(const int* __restrict__ rowptr,
                                   const int* __restrict__ col,
                                   const float* __restrict__ as_v,
                                   const float* __restrict__ ad_v,
                                   const __half* __restrict__ h,
                                   __half* __restrict__ out, int n) {
    int node = (blockIdx.x * blockDim.x + threadIdx.x) >> 5;
    if (node >= n) return;
    int lane = threadIdx.x & 31;
    int slot = lane & 7;
    int half = lane >> 4;            // 0: even edges, 1: odd edges
    int cbase = (lane & 15) * 8;     // 8 cols per lane

    float advv = __ldg(ad_v + node);
    int beg = __ldg(rowptr + node);
    int end = __ldg(rowptr + node + 1);

    const float NEG_INF = __int_as_float(0xFF800000);
    float denp = 0.0f;
    float acc[8];
#pragma unroll
    for (int k = 0; k < 8; k++) acc[k] = 0.f;

    for (int i = beg; i < end; i += 8) {
        int idx = i + slot;
        bool eact = idx < end;
        int sc = __ldg(col + (eact ? idx : beg));
        float e = eact ? (__ldg(as_v + sc) + advv) : NEG_INF;
        e = e > 0.f ? e : 0.2f * e;
        float wgt = __expf(e);       // 0 for tail edges
        denp += wgt;

        // 4 steps x 2 edges: low half handles edge 2t, high half edge 2t+1
        uint4 hb[4];
        float wj[4];
#pragma unroll
        for (int t = 0; t < 4; t++) {
            int esel = 2 * t + half;                  // source lane = slot esel
            int sj = __shfl_sync(FULLM, sc, esel);
            wj[t]  = __shfl_sync(FULLM, wgt, esel);
            hb[t]  = *(const uint4*)(h + (size_t)sj * HID + cbase);
        }
#pragma unroll
        for (int t = 0; t < 4; t++) {
            __half2* hp = (__half2*)&hb[t];
#pragma unroll
            for (int q = 0; q < 4; q++) {
                float2 f = __half22float2(hp[q]);
                acc[2 * q]     = fmaf(wj[t], f.x, acc[2 * q]);
                acc[2 * q + 1] = fmaf(wj[t], f.y, acc[2 * q + 1]);
            }
        }
    }

    // combine even/odd halves (lanes L and L+16 hold same columns)
#pragma unroll
    for (int k = 0; k < 8; k++)
        acc[k] += __shfl_xor_sync(FULLM, acc[k], 16);

    denp += __shfl_xor_sync(FULLM, denp, 1, 8);
    denp += __shfl_xor_sync(FULLM, denp, 2, 8);
    denp += __shfl_xor_sync(FULLM, denp, 4, 8);

    if (lane < 16) {
        float inv = 1.0f / denp;
        __half2 o[4];
#pragma unroll
        for (int q = 0; q < 4; q++)
            o[q] = __floats2half2_rn(acc[2 * q] * inv, acc[2 * q + 1] * inv);
        *(uint4*)(out + (size_t)node * HID + cbase) = *(uint4*)o;
    }
}

// ---- layer-2 wmma GEMM + fused layer-3 GEMM --------------------------------
__global__ __launch_bounds__(128) void wmma_fused_kernel(
        const __half* __restrict__ A,
        const __half* __restrict__ Wh,
        const __half* __restrict__ Wh3,
        const float* __restrict__ bias,
        const float* __restrict__ ws3,
        const float* __restrict__ wd3,
        __half* __restrict__ h16,
        float* __restrict__ as_o,
        float* __restrict__ ad_o, int nPad, int n) {
    __shared__ float  s_c[64 * HID];
    __shared__ __half s_ch[64 * HID];
    int warp = threadIdx.x >> 5;
    int lane = threadIdx.x & 31;
    int row0 = blockIdx.x * 64 + warp * 16;
    if (row0 >= nPad) return;

    wmma::fragment<wmma::accumulator, 16, 16, 16, float> acc[8];
#pragma unroll
    for (int i = 0; i < 8; i++) wmma::fill_fragment(acc[i], 0.f);

#pragma unroll
    for (int k = 0; k < 8; k++) {
        wmma::fragment<wmma::matrix_a, 16, 16, 16, __half, wmma::row_major> a;
        wmma::load_matrix_sync(a, A + (size_t)row0 * HID + k * 16, HID);
#pragma unroll
        for (int nt = 0; nt < 8; nt++) {
            wmma::fragment<wmma::matrix_b, 16, 16, 16, __half, wmma::row_major> b;
            wmma::load_matrix_sync(b, Wh + k * 16 * HID + nt * 16, HID);
            wmma::mma_sync(acc[nt], a, b, acc[nt]);
        }
    }
    float*  my  = s_c  + warp * 16 * HID;
    __half* myh = s_ch + warp * 16 * HID;
#pragma unroll
    for (int nt = 0; nt < 8; nt++)
        wmma::store_matrix_sync(my + nt * 16, acc[nt], HID, wmma::mem_row_major);
    __syncwarp();

    float4 bv = *(const float4*)(bias + lane * 4);
    float4 sv = *(const float4*)(ws3 + lane * 4);
    float4 dv = *(const float4*)(wd3 + lane * 4);
#pragma unroll
    for (int r = 0; r < 16; r++) {
        int row = row0 + r;
        float4 v = *(const float4*)(my + r * HID + lane * 4);
        float ox = fmaxf(v.x + bv.x, 0.f);
        float oy = fmaxf(v.y + bv.y, 0.f);
        float oz = fmaxf(v.z + bv.z, 0.f);
        float ow = fmaxf(v.w + bv.w, 0.f);
        __half2 p0 = __floats2half2_rn(ox, oy);
        __half2 p1 = __floats2half2_rn(oz, ow);
        uint2 packed = make_uint2(*(unsigned*)&p0, *(unsigned*)&p1);
        *(uint2*)(myh + r * HID + lane * 4) = packed;
        if (row < n) {
            float ps = ox * sv.x + oy * sv.y + oz * sv.z + ow * sv.w;
            float pd = ox * dv.x + oy * dv.y + oz * dv.z + ow * dv.w;
#pragma unroll
            for (int o = 16; o > 0; o >>= 1) {
                ps += __shfl_xor_sync(FULLM, ps, o);
                pd += __shfl_xor_sync(FULLM, pd, o);
            }
            if (lane == 0) { as_o[row] = ps; ad_o[row] = pd; }
        }
    }
    __syncwarp();

    wmma::fragment<wmma::accumulator, 16, 16, 16, float> acc3;
    wmma::fill_fragment(acc3, 0.f);
#pragma unroll
    for (int k = 0; k < 8; k++) {
        wmma::fragment<wmma::matrix_a, 16, 16, 16, __half, wmma::row_major> a;
        wmma::load_matrix_sync(a, myh + k * 16, HID);
        wmma::fragment<wmma::matrix_b, 16, 16, 16, __half, wmma::row_major> b;
        wmma::load_matrix_sync(b, Wh3 + k * 16 * NC, NC);
        wmma::mma_sync(acc3, a, b, acc3);
    }
    wmma::store_matrix_sync(my, acc3, NC, wmma::mem_row_major);
    __syncwarp();
#pragma unroll
    for (int q = 0; q < 8; q++) {
        int idx = q * 32 + lane;
        h16[(size_t)row0 * NC + idx] = __float2half_rn(my[idx]);
    }
}

// ------------- fused aggregation C=16 + pooling (layer 3) -------------------
__global__ void fused_aggr16_pool_kernel(const int* __restrict__ rowptr,
                                         const int* __restrict__ col,
                                         const float* __restrict__ as_v,
                                         const float* __restrict__ ad_v,
                                         const __half* __restrict__ h,
                                         const float* __restrict__ bias,
                                         const int* __restrict__ batch,
                                         float* __restrict__ pool,
                                         float* __restrict__ cnt, int n) {
    int w = (blockIdx.x * blockDim.x + threadIdx.x) >> 5;
    int lane = threadIdx.x & 31;
    int local = lane & 15;
    int slot = lane & 7;
    int node = w * 2 + (lane >> 4);
    int c = local;
    bool active = node < n;

    float advv = active ? __ldg(ad_v + node) : 0.f;
    int beg = active ? __ldg(rowptr + node) : 0;
    int end = active ? __ldg(rowptr + node + 1) : 0;

    int iters = (end - beg + 7) >> 3;
    int oiters = __shfl_xor_sync(FULLM, iters, 16);
    int maxIters = iters > oiters ? iters : oiters;

    const float NEG_INF = __int_as_float(0xFF800000);
    float denp = 0.0f, acc = 0.0f;

    for (int it = 0; it < maxIters; it++) {
        int idx = beg + it * 8 + slot;
        bool eact = idx < end;
        int sc = __ldg(col + (eact ? idx : 0));
        float e = eact ? (__ldg(as_v + sc) + advv) : NEG_INF;
        e = e > 0.f ? e : 0.2f * e;
        float wgt = __expf(e);
        denp += wgt;

        float hb[8];
#pragma unroll
        for (int j = 0; j < 8; j++) {
            int sj = __shfl_sync(FULLM, sc, j, 16);
            hb[j] = __half2float(__ldg(h + (size_t)sj * NC + c));
        }
#pragma unroll
        for (int j = 0; j < 8; j++) {
            float wj = __shfl_sync(FULLM, wgt, j, 16);
            acc = fmaf(wj, hb[j], acc);
        }
    }

    denp += __shfl_xor_sync(FULLM, denp, 1, 8);
    denp += __shfl_xor_sync(FULLM, denp, 2, 8);
    denp += __shfl_xor_sync(FULLM, denp, 4, 8);

    if (active) {
        float val = fmaxf(acc / denp + __ldg(bias + c), 0.f);
        int g = __ldg(batch + node);
        atomicAdd(&pool[g * NC + c], val);
        if (c == 0) atomicAdd(&cnt[g], 1.0f);
    }
}

__global__ void finalize_kernel(const float* __restrict__ pool,
                                const float* __restrict__ cnt,
                                float* __restrict__ outp) {
    int t = blockIdx.x * blockDim.x + threadIdx.x;
    if (t >= NG * NC) return;
    int g = t >> 4;
    float v = pool[t] / fmaxf(cnt[g], 1.0f);
    outp[t] = 1.0f / (1.0f + expf(-v));
}

// ---------------------------------------------------------------------------

extern "C" void kernel_launch(void* const* d_in, const int* in_sizes, int n_in,
                              void* d_out, int out_size) {
    const float* x     = (const float*)d_in[0];
    const int*   ei    = (const int*)  d_in[1];
    const int*   batch = (const int*)  d_in[3];
    const float* W1  = (const float*)d_in[4];
    const float* as1 = (const float*)d_in[5];
    const float* ad1 = (const float*)d_in[6];
    const float* b1  = (const float*)d_in[7];
    const float* W2  = (const float*)d_in[8];
    const float* as2 = (const float*)d_in[9];
    const float* ad2 = (const float*)d_in[10];
    const float* b2  = (const float*)d_in[11];
    const float* W3  = (const float*)d_in[12];
    const float* as3 = (const float*)d_in[13];
    const float* ad3 = (const float*)d_in[14];
    const float* b3  = (const float*)d_in[15];
    float* out = (float*)d_out;

    int n    = in_sizes[0] / F_IN;
    int E    = in_sizes[1] / 2;
    int Etot = E + n;
    const int* src = ei;
    const int* dst = ei + E;

    float *pas, *pad, *ppool, *pcnt, *pG1;
    float *pws1, *pwd1, *pws2, *pwd2, *pws3, *pwd3;
    __half *pA, *pG2, *ph16, *pWh, *pWh3;
    int *pdeg, *prow, *pcur, *pcol, *ppart;
    cudaGetSymbolAddress((void**)&pA,    g_A);
    cudaGetSymbolAddress((void**)&pG2,   g_G2);
    cudaGetSymbolAddress((void**)&ph16,  g_h16);
    cudaGetSymbolAddress((void**)&pWh,   g_Wh);
    cudaGetSymbolAddress((void**)&pWh3,  g_Wh3);
    cudaGetSymbolAddress((void**)&pG1,   g_G1);
    cudaGetSymbolAddress((void**)&pas,   g_as);
    cudaGetSymbolAddress((void**)&pad,   g_ad);
    cudaGetSymbolAddress((void**)&pws1,  g_ws1);
    cudaGetSymbolAddress((void**)&pwd1,  g_wd1);
    cudaGetSymbolAddress((void**)&pws2,  g_ws2);
    cudaGetSymbolAddress((void**)&pwd2,  g_wd2);
    cudaGetSymbolAddress((void**)&pws3,  g_ws3);
    cudaGetSymbolAddress((void**)&pwd3,  g_wd3);
    cudaGetSymbolAddress((void**)&ppool, g_pool);
    cudaGetSymbolAddress((void**)&pcnt,  g_cnt);
    cudaGetSymbolAddress((void**)&pdeg,  g_deg);
    cudaGetSymbolAddress((void**)&prow,  g_rowptr);
    cudaGetSymbolAddress((void**)&pcur,  g_cursor);
    cudaGetSymbolAddress((void**)&pcol,  g_col);
    cudaGetSymbolAddress((void**)&ppart, g_partial);

    const int TB = 256;
    int nPad     = (n + 127) & ~127;
    int nb       = (n + SCAN_CHUNK - 1) / SCAN_CHUNK;
    int gN       = (n + TB - 1) / TB;
    int gEdge8   = (Etot + TB * 8 - 1) / (TB * 8);
    int warps128 = (n + 7) / 8;
    int gGemmK11 = (warps128 * 32 + TB - 1) / TB;
    int gWmma    = nPad / 64;
    int gNodeWarp= (n * 32 + TB - 1) / TB;
    int gHalfWarp= (((n + 1) / 2) * 32 + TB - 1) / TB;
    int gPool    = (NG * NC + TB - 1) / TB;

    setup_kernel<<<gN + 74, TB>>>(W1, as1, ad1, W2, as2, ad2, W3, as3, ad3,
                                  pws1, pwd1, pws2, pwd2, pws3, pwd3,
                                  pWh, pWh3, pdeg, ppool, pcnt, n, gN);
    count_asad_kernel<<<gEdge8 + gN, TB>>>(dst, E, Etot, pdeg, x, pws1, pwd1,
                                           pas, pad, n, gEdge8);
    scan_partial_kernel<<<nb, 256>>>(pdeg, ppart, n);
    scan_final_kernel<<<nb, 256>>>(pdeg, ppart, prow, pcur, n, nb);
    scatter_kernel<<<gEdge8, TB>>>(src, dst, E, Etot, pcur, pcol);

    aggr11_kernel<<<gHalfWarp, TB>>>(prow, pcol, pas, pad, x, pG1, n);
    gemmK11_kernel<<<gGemmK11, TB>>>(pG1, W1, b1, pws2, pwd2, pA, pas, pad, n);

    aggr128_raw_kernel<<<gNodeWarp, TB>>>(prow, pcol, pas, pad, pA, pG2, n);
    wmma_fused_kernel<<<gWmma, 128>>>(pG2, pWh, pWh3, b2, pws3, pwd3,
                                      ph16, pas, pad, nPad, n);

    fused_aggr16_pool_kernel<<<gHalfWarp, TB>>>(prow, pcol, pas, pad, ph16, b3,
                                                batch, ppool, pcnt, n);
    finalize_kernel<<<gPool, TB>>>(ppool, pcnt, out);
}